// round 1
// baseline (speedup 1.0000x reference)
#include <cuda_runtime.h>
#include <cstdint>

// CentroidDistance: B=32, N=4096, E=64, C=256
// out layout: [0:8192) graph_dist (B,C), [8192:) dist (B,N,C)

#define BB 32
#define NN 4096
#define EE 64
#define CC 256
#define TILE 32
#define NTILES (NN / TILE)   // 128
#define EPSF 1e-6f

// cs[c][66] padded + xs[32][64] + x2s/rxs/mks[32] + sc2/src[256]
#define CS_STRIDE 66
#define SMEM_FLOATS (CC * CS_STRIDE + TILE * EE + 3 * TILE + 2 * CC)
#define SMEM_BYTES (SMEM_FLOATS * 4)

typedef unsigned long long ull;

__device__ float g_masksum[BB];
__device__ float g_c2[CC];
__device__ float g_rc[CC];
__device__ float g_partial[(size_t)BB * NTILES * CC];

__device__ __forceinline__ void ffma2(ull& d, ull a, ull b) {
    asm("fma.rn.f32x2 %0, %1, %2, %0;" : "+l"(d) : "l"(a), "l"(b));
}

// ---------------- prep: mask sums per batch + centroid stats ----------------
__global__ void prep_kernel(const float* __restrict__ mask,
                            const float* __restrict__ cent) {
    __shared__ float red[256];
    int t = threadIdx.x;
    int blk = blockIdx.x;
    if (blk < BB) {
        float s = 0.0f;
        const float* mp = mask + blk * NN;
        for (int i = t; i < NN; i += 256) s += mp[i];
        red[t] = s;
        __syncthreads();
        for (int o = 128; o > 0; o >>= 1) {
            if (t < o) red[t] += red[t + o];
            __syncthreads();
        }
        if (t == 0) g_masksum[blk] = red[0];
    } else {
        if (t < CC) {
            float s = 0.0f;
            const float* cp = cent + t * EE;
#pragma unroll
            for (int e = 0; e < EE; e++) s += cp[e] * cp[e];
            g_c2[t] = s;
            g_rc[t] = 1.0f / fmaxf(1.0f - s, 1e-12f);
        }
    }
}

// ---------------- main: dist tile + per-block partial sums ----------------
__global__ __launch_bounds__(256, 2) void dist_kernel(
    const float* __restrict__ x, const float* __restrict__ mask,
    const float* __restrict__ cent, float* __restrict__ out) {
    extern __shared__ float sm[];
    float* cs  = sm;                       // CC * 66
    float* xs  = cs + CC * CS_STRIDE;      // 32 * 64
    float* x2s = xs + TILE * EE;           // 32
    float* rxs = x2s + TILE;               // 32
    float* mks = rxs + TILE;               // 32
    float* sc2 = mks + TILE;               // 256
    float* src = sc2 + CC;                 // 256

    int t = threadIdx.x;
    int b = blockIdx.y;
    int tile = blockIdx.x;
    int row0 = tile * TILE;

    // Stage centroids: global float4 coalesced -> padded smem [c][66]
    {
        const float4* c4 = (const float4*)cent;
#pragma unroll
        for (int i = 0; i < 16; i++) {
            int idx = t + i * 256;          // 0..4095 float4s
            float4 v = c4[idx];
            int c = idx >> 4;               // 16 float4 per centroid row
            int e = (idx & 15) * 4;
            float* dst = &cs[c * CS_STRIDE + e];
            *(float2*)dst       = make_float2(v.x, v.y);
            *(float2*)(dst + 2) = make_float2(v.z, v.w);
        }
    }
    if (t < CC) { sc2[t] = g_c2[t]; src[t] = g_rc[t]; }

    // Stage x tile (32 rows x 64) + per-row x2 via shfl reduce (8 threads/row)
    {
        const float4* x4 = (const float4*)(x + (size_t)(b * NN + row0) * EE);
        float p = 0.0f;
#pragma unroll
        for (int i = 0; i < 2; i++) {
            int f = t * 2 + i;              // 0..511 float4s, both in same row
            float4 v = x4[f];
            *(float4*)&xs[f * 4] = v;
            p += v.x * v.x + v.y * v.y + v.z * v.z + v.w * v.w;
        }
        p += __shfl_xor_sync(0xffffffffu, p, 1);
        p += __shfl_xor_sync(0xffffffffu, p, 2);
        p += __shfl_xor_sync(0xffffffffu, p, 4);
        if ((t & 7) == 0) {
            int r = t >> 3;
            x2s[r] = p;
            rxs[r] = 1.0f / fmaxf(1.0f - p, 1e-12f);
        }
        if (t < TILE) mks[t] = mask[b * NN + row0 + t];
    }
    __syncthreads();

    int q = t & 63;         // centroid lane: handles c = q, q+64, q+128, q+192
    int g = t >> 6;         // row group: rows rbase..rbase+7
    int rbase = g * 8;

    ull acc[8][4];
#pragma unroll
    for (int r = 0; r < 8; r++)
#pragma unroll
        for (int j = 0; j < 4; j++) acc[r][j] = 0ull;

    const float* cq0 = &cs[q * CS_STRIDE];
    const float* cq1 = &cs[(q + 64) * CS_STRIDE];
    const float* cq2 = &cs[(q + 128) * CS_STRIDE];
    const float* cq3 = &cs[(q + 192) * CS_STRIDE];
    const float* xrow = &xs[rbase * EE];

#pragma unroll 4
    for (int e2 = 0; e2 < 32; e2++) {
        ull cv0 = *(const ull*)&cq0[2 * e2];
        ull cv1 = *(const ull*)&cq1[2 * e2];
        ull cv2 = *(const ull*)&cq2[2 * e2];
        ull cv3 = *(const ull*)&cq3[2 * e2];
#pragma unroll
        for (int r = 0; r < 8; r++) {
            ull xv = *(const ull*)&xrow[r * EE + 2 * e2];
            ffma2(acc[r][0], xv, cv0);
            ffma2(acc[r][1], xv, cv1);
            ffma2(acc[r][2], xv, cv2);
            ffma2(acc[r][3], xv, cv3);
        }
    }

    // Epilogue: sq -> arg -> arccosh -> mask, store dist, accumulate col sums
    float sumc[4] = {0.0f, 0.0f, 0.0f, 0.0f};
    int cidx[4];
    float c2v[4], rcv[4];
#pragma unroll
    for (int j = 0; j < 4; j++) {
        cidx[j] = q + 64 * j;
        c2v[j] = sc2[cidx[j]];
        rcv[j] = src[cidx[j]];
    }
#pragma unroll
    for (int r = 0; r < 8; r++) {
        int row = row0 + rbase + r;
        float x2 = x2s[rbase + r];
        float rx = rxs[rbase + r];
        float mk = mks[rbase + r];
        float* orow = out + (size_t)8192 + (size_t)(b * NN + row) * CC;
#pragma unroll
        for (int j = 0; j < 4; j++) {
            ull a = acc[r][j];
            float lo = __uint_as_float((unsigned)a);
            float hi = __uint_as_float((unsigned)(a >> 32));
            float dot = lo + hi;
            float sq = fmaxf(x2 + c2v[j] - 2.0f * dot, 0.0f);
            float tt = 2.0f * sq * rx * rcv[j];     // arg - 1
            tt = fmaxf(tt, EPSF);
            float s2 = tt * (tt + 2.0f);            // arg^2 - 1, stable
            float s;
            asm("sqrt.approx.f32 %0, %1;" : "=f"(s) : "f"(s2));
            float u = 1.0f + tt + s;
            float lg;
            asm("lg2.approx.f32 %0, %1;" : "=f"(lg) : "f"(u));
            float d = 0.69314718055994531f * lg * mk;
            sumc[j] += d;
            orow[cidx[j]] = d;
        }
    }

    // Deterministic per-block column sums (no float atomics): reuse xs as red[4][256]
    __syncthreads();
    float* red = xs;
#pragma unroll
    for (int j = 0; j < 4; j++) red[g * CC + cidx[j]] = sumc[j];
    __syncthreads();
    if (t < CC) {
        float v = red[t] + red[CC + t] + red[2 * CC + t] + red[3 * CC + t];
        g_partial[(size_t)(b * NTILES + tile) * CC + t] = v;
    }
}

// ---------------- finalize: graph_dist = sum(dist)/sum(mask) ----------------
__global__ void finalize_kernel(float* __restrict__ out) {
    int b = blockIdx.x;
    int c = threadIdx.x;
    const float* p = g_partial + (size_t)b * NTILES * CC + c;
    float s = 0.0f;
#pragma unroll 8
    for (int i = 0; i < NTILES; i++) s += p[(size_t)i * CC];
    out[b * CC + c] = s / g_masksum[b];
}

extern "C" void kernel_launch(void* const* d_in, const int* in_sizes, int n_in,
                              void* d_out, int out_size) {
    const float* x    = (const float*)d_in[0];   // node_repr (B,N,E)
    const float* mask = (const float*)d_in[1];   // mask (B,N,1)
    const float* cent = (const float*)d_in[2];   // centroid (C,E)
    float* out = (float*)d_out;

    cudaFuncSetAttribute(dist_kernel,
                         cudaFuncAttributeMaxDynamicSharedMemorySize, SMEM_BYTES);

    prep_kernel<<<BB + 1, 256>>>(mask, cent);
    dist_kernel<<<dim3(NTILES, BB), 256, SMEM_BYTES>>>(x, mask, cent, out);
    finalize_kernel<<<BB, CC>>>(out);
}

// round 4
// speedup vs baseline: 1.5843x; 1.5843x over previous
#include <cuda_runtime.h>
#include <cuda_fp16.h>
#include <cstdint>

// CentroidDistance: B=32, N=4096, E=64, C=256
// out: [0:8192) graph_dist (B,C), [8192:) dist (B,N,C)
// Path: ldmatrix + mma.sync m16n8k16 fp16 (compute_103-safe), fp32 epilogue,
// direct sector-aligned global stores, deterministic column sums.
// R4 fix: k-step fragment advance must be XOR (swizzle commutes), not ADD.

#define BB 32
#define NN 4096
#define EE 64
#define CC 256
#define TILE_M 128
#define NTILES (NN / TILE_M)     // 32
#define THREADS 512
#define EPSF 1e-6f

#define A_OFF 0
#define B_OFF 16384
#define F_BASE (49152 / 4)
#define X2S_OFF (F_BASE)
#define RXS_OFF (F_BASE + 128)
#define MKS_OFF (F_BASE + 256)
#define C2S_OFF (F_BASE + 384)
#define RCS_OFF (F_BASE + 640)
#define RED_OFF (F_BASE + 896)
#define SMEM_BYTES ((RED_OFF + 4 * 256) * 4)   // 56832

__device__ float g_partial[(size_t)BB * NTILES * CC];

__device__ __forceinline__ uint32_t smem_u32(const void* p) {
    uint32_t a;
    asm("{ .reg .u64 t; cvta.to.shared.u64 t, %1; cvt.u32.u64 %0, t; }" : "=r"(a) : "l"(p));
    return a;
}
__device__ __forceinline__ uint32_t sw128(uint32_t off) {
    return off ^ ((off >> 3) & 0x70);
}
__device__ __forceinline__ void ldm_x4(uint32_t* r, uint32_t addr) {
    asm volatile("ldmatrix.sync.aligned.m8n8.x4.shared.b16 {%0,%1,%2,%3}, [%4];"
        : "=r"(r[0]), "=r"(r[1]), "=r"(r[2]), "=r"(r[3]) : "r"(addr));
}
__device__ __forceinline__ void mma16816(float* d, const uint32_t* a, uint32_t b0, uint32_t b1) {
    asm volatile("mma.sync.aligned.m16n8k16.row.col.f32.f16.f16.f32 "
        "{%0,%1,%2,%3}, {%4,%5,%6,%7}, {%8,%9}, {%0,%1,%2,%3};"
        : "+f"(d[0]), "+f"(d[1]), "+f"(d[2]), "+f"(d[3])
        : "r"(a[0]), "r"(a[1]), "r"(a[2]), "r"(a[3]), "r"(b0), "r"(b1));
}
__device__ __forceinline__ float acosh_dist(float dot, float x2, float rx,
                                            float c2, float rc, float mk) {
    float sq = fmaxf(x2 + c2 - 2.0f * dot, 0.0f);
    float tt = fmaxf(2.0f * sq * rx * rc, EPSF);      // arg - 1
    float s2 = tt * (tt + 2.0f);                       // arg^2 - 1
    float s;
    asm("sqrt.approx.f32 %0, %1;" : "=f"(s) : "f"(s2));
    float u = 1.0f + tt + s;
    float lg;
    asm("lg2.approx.f32 %0, %1;" : "=f"(lg) : "f"(u));
    return 0.69314718055994531f * lg * mk;
}

__global__ __launch_bounds__(THREADS, 2) void dist_kernel(
    const float* __restrict__ x, const float* __restrict__ mask,
    const float* __restrict__ cent, float* __restrict__ out) {
    extern __shared__ char smem[];
    uint32_t sb = smem_u32(smem);
    float* smf = (float*)smem;

    int tid = threadIdx.x;
    int lane = tid & 31;
    int wid = tid >> 5;
    int b = blockIdx.y, tile = blockIdx.x;
    int row0 = tile * TILE_M;

    float* x2s = smf + X2S_OFF;
    float* rxs = smf + RXS_OFF;
    float* mks = smf + MKS_OFF;
    float* c2s = smf + C2S_OFF;
    float* rcs = smf + RCS_OFF;
    float* red = smf + RED_OFF;

    // ---- stage A (x tile): 1024 16B-chunks, fp32->fp16, SW128 STS + row x2 ----
    {
        const float4* x4 = (const float4*)(x + ((size_t)b * NN + row0) * EE);
#pragma unroll
        for (int it = 0; it < 2; it++) {
            int chunk = tid + it * THREADS;        // 0..1023
            int row = chunk >> 3, kc = chunk & 7;
            float4 v0 = x4[chunk * 2];
            float4 v1 = x4[chunk * 2 + 1];
            float p = v0.x * v0.x + v0.y * v0.y + v0.z * v0.z + v0.w * v0.w
                    + v1.x * v1.x + v1.y * v1.y + v1.z * v1.z + v1.w * v1.w;
            p += __shfl_xor_sync(0xffffffffu, p, 1);
            p += __shfl_xor_sync(0xffffffffu, p, 2);
            p += __shfl_xor_sync(0xffffffffu, p, 4);
            if ((lane & 7) == 0) {
                x2s[row] = p;
                rxs[row] = 1.0f / fmaxf(1.0f - p, 1e-12f);
            }
            union { __half2 h[4]; uint4 u; } pk;
            pk.h[0] = __floats2half2_rn(v0.x, v0.y);
            pk.h[1] = __floats2half2_rn(v0.z, v0.w);
            pk.h[2] = __floats2half2_rn(v1.x, v1.y);
            pk.h[3] = __floats2half2_rn(v1.z, v1.w);
            *(uint4*)(smem + A_OFF + sw128((uint32_t)(row * 128 + kc * 16))) = pk.u;
        }
        if (tid < TILE_M) mks[tid] = mask[b * NN + row0 + tid];
    }
    // ---- stage B (centroids 256x64): 2048 chunks ----
    {
        const float4* c4 = (const float4*)cent;
#pragma unroll
        for (int it = 0; it < 4; it++) {
            int chunk = tid + it * THREADS;        // 0..2047
            int row = chunk >> 3, kc = chunk & 7;
            float4 v0 = c4[chunk * 2];
            float4 v1 = c4[chunk * 2 + 1];
            float p = v0.x * v0.x + v0.y * v0.y + v0.z * v0.z + v0.w * v0.w
                    + v1.x * v1.x + v1.y * v1.y + v1.z * v1.z + v1.w * v1.w;
            p += __shfl_xor_sync(0xffffffffu, p, 1);
            p += __shfl_xor_sync(0xffffffffu, p, 2);
            p += __shfl_xor_sync(0xffffffffu, p, 4);
            if ((lane & 7) == 0) {
                c2s[row] = p;
                rcs[row] = 1.0f / fmaxf(1.0f - p, 1e-12f);
            }
            union { __half2 h[4]; uint4 u; } pk;
            pk.h[0] = __floats2half2_rn(v0.x, v0.y);
            pk.h[1] = __floats2half2_rn(v0.z, v0.w);
            pk.h[2] = __floats2half2_rn(v1.x, v1.y);
            pk.h[3] = __floats2half2_rn(v1.z, v1.w);
            *(uint4*)(smem + B_OFF + sw128((uint32_t)(row * 128 + kc * 16))) = pk.u;
        }
    }
    __syncthreads();

    // ---- warp tile: rows [mrow0, +32), cols [ncol0, +64) ----
    int mrow0 = (wid & 3) * 32;
    int ncol0 = (wid >> 2) * 64;

    float acc[2][8][4];
#pragma unroll
    for (int i = 0; i < 2; i++)
#pragma unroll
        for (int j = 0; j < 8; j++)
#pragma unroll
            for (int q = 0; q < 4; q++) acc[i][j][q] = 0.0f;

    // ldmatrix base addresses at kc=0.
    // k-step advance: base col bits 5-6 are zero, so sw(off + kc*32) = sw(off) ^ (kc*32).
    uint32_t addrA[2], addrB[4];
#pragma unroll
    for (int i = 0; i < 2; i++) {
        int r = mrow0 + i * 16 + (lane & 15);
        int ch = (lane >> 4);                       // k-chunk 0/1 (16B)
        addrA[i] = sb + A_OFF + sw128((uint32_t)(r * 128 + ch * 16));
    }
#pragma unroll
    for (int jp = 0; jp < 4; jp++) {
        int n = ncol0 + jp * 16 + (lane & 7) + ((lane >> 4) << 3);
        int ch = (lane >> 3) & 1;
        addrB[jp] = sb + B_OFF + sw128((uint32_t)(n * 128 + ch * 16));
    }

#pragma unroll
    for (int kc = 0; kc < 4; kc++) {
        uint32_t af[2][4], bf[4][4];
#pragma unroll
        for (int i = 0; i < 2; i++) ldm_x4(af[i], addrA[i] ^ (uint32_t)(kc * 32));
#pragma unroll
        for (int jp = 0; jp < 4; jp++) ldm_x4(bf[jp], addrB[jp] ^ (uint32_t)(kc * 32));
#pragma unroll
        for (int i = 0; i < 2; i++)
#pragma unroll
            for (int j = 0; j < 8; j++)
                mma16816(acc[i][j], af[i], bf[j >> 1][(j & 1) * 2], bf[j >> 1][(j & 1) * 2 + 1]);
    }

    // ---- epilogue: arccosh + direct stores (32B sectors) + column sums ----
    float sumc[8][2];
#pragma unroll
    for (int j = 0; j < 8; j++) sumc[j][0] = sumc[j][1] = 0.0f;

    float* obase = out + 8192 + ((size_t)b * NN + row0) * CC;
#pragma unroll
    for (int i = 0; i < 2; i++) {
        int ra = mrow0 + i * 16 + (lane >> 2);
        int rb = ra + 8;
        float x2a = x2s[ra], rxa = rxs[ra], mka = mks[ra];
        float x2b = x2s[rb], rxb = rxs[rb], mkb = mks[rb];
        float* rowa = obase + (size_t)ra * CC;
        float* rowb = obase + (size_t)rb * CC;
#pragma unroll
        for (int j = 0; j < 8; j++) {
            int c = ncol0 + j * 8 + (lane & 3) * 2;
            float2 c2v = *(const float2*)&c2s[c];
            float2 rcv = *(const float2*)&rcs[c];
            float v0 = acosh_dist(acc[i][j][0], x2a, rxa, c2v.x, rcv.x, mka);
            float v1 = acosh_dist(acc[i][j][1], x2a, rxa, c2v.y, rcv.y, mka);
            float v2 = acosh_dist(acc[i][j][2], x2b, rxb, c2v.x, rcv.x, mkb);
            float v3 = acosh_dist(acc[i][j][3], x2b, rxb, c2v.y, rcv.y, mkb);
            *(float2*)&rowa[c] = make_float2(v0, v1);
            *(float2*)&rowb[c] = make_float2(v2, v3);
            sumc[j][0] += v0 + v2;
            sumc[j][1] += v1 + v3;
        }
    }

    // reduce column sums over the 8 lane-groups sharing the same columns
#pragma unroll
    for (int j = 0; j < 8; j++) {
#pragma unroll
        for (int o = 4; o < 32; o <<= 1) {
            sumc[j][0] += __shfl_xor_sync(0xffffffffu, sumc[j][0], o);
            sumc[j][1] += __shfl_xor_sync(0xffffffffu, sumc[j][1], o);
        }
    }
    if (lane < 4) {
        int g = wid & 3;
#pragma unroll
        for (int j = 0; j < 8; j++)
            *(float2*)&red[g * CC + ncol0 + j * 8 + lane * 2] =
                make_float2(sumc[j][0], sumc[j][1]);
    }
    __syncthreads();
    if (tid < CC) {
        float v = red[tid] + red[CC + tid] + red[2 * CC + tid] + red[3 * CC + tid];
        g_partial[((size_t)b * NTILES + tile) * CC + tid] = v;
    }
}

// ---------------- finalize: mask sum + graph_dist ----------------
__global__ void finalize_kernel(const float* __restrict__ mask,
                                float* __restrict__ out) {
    __shared__ float redm[256];
    int b = blockIdx.x, t = threadIdx.x;
    float s = 0.0f;
    const float* mp = mask + b * NN;
    for (int i = t; i < NN; i += 256) s += mp[i];
    redm[t] = s;
    __syncthreads();
    for (int o = 128; o > 0; o >>= 1) {
        if (t < o) redm[t] += redm[t + o];
        __syncthreads();
    }
    float acc = 0.0f;
    const float* p = g_partial + (size_t)b * NTILES * CC + t;
#pragma unroll
    for (int i = 0; i < NTILES; i++) acc += p[(size_t)i * CC];
    out[b * CC + t] = acc / redm[0];
}

extern "C" void kernel_launch(void* const* d_in, const int* in_sizes, int n_in,
                              void* d_out, int out_size) {
    const float* x    = (const float*)d_in[0];   // node_repr (B,N,E)
    const float* mask = (const float*)d_in[1];   // mask (B,N,1)
    const float* cent = (const float*)d_in[2];   // centroid (C,E)
    float* out = (float*)d_out;

    cudaFuncSetAttribute(dist_kernel,
                         cudaFuncAttributeMaxDynamicSharedMemorySize, SMEM_BYTES);

    dist_kernel<<<dim3(NTILES, BB), THREADS, SMEM_BYTES>>>(x, mask, cent, out);
    finalize_kernel<<<BB, CC>>>(mask, out);
}